// round 1
// baseline (speedup 1.0000x reference)
#include <cuda_runtime.h>

// Problem shape (fixed per metadata):
//   X0 [4,1024,256] f32, t [4,1] f32, Wc_w [128,256] f32, Wc_b [128] f32,
//   w [128] f32, A [64,128,6] f32, Bp [64,128,6] f32  ->  out [4,1024,64] f32
#define B_   4
#define S_   1024
#define ROWS 4096        // B_*S_
#define DIN  256
#define Q_   128
#define KF   6
#define DOUT 64
#define NF   (Q_*KF*2)   // 1536 features

// Scratch (no allocs allowed)
__device__ float g_angle[ROWS * Q_];             // 2 MB
__device__ float g_afold[Q_ * KF * 2 * DOUT];    // 384 KB, layout [(q*6+k)*2 + {0:sin,1:cos}][d]

// ---------------------------------------------------------------------------
// Kernel 1: fold A,Bp into the two coefficient matrices for the sin/cos basis
// ---------------------------------------------------------------------------
__global__ void fold_kernel(const float* __restrict__ A, const float* __restrict__ Bp) {
    int i = blockIdx.x * blockDim.x + threadIdx.x;       // over DOUT*Q_*KF = 49152
    if (i >= DOUT * Q_ * KF) return;
    int d   = i / (Q_ * KF);
    int rem = i - d * (Q_ * KF);
    int q   = rem / KF;
    int k   = rem - q * KF;
    float a = A[i], b = Bp[i];
    float sb, cb;
    sincosf(b, &sb, &cb);
    int f = (q * KF + k) * 2;
    g_afold[f * DOUT + d]       = a * cb;   // multiplies sin(k*angle)
    g_afold[(f + 1) * DOUT + d] = a * sb;   // multiplies cos(k*angle)
}

// ---------------------------------------------------------------------------
// Kernel 2: angle[row][q] = X0[row,:] . Wc_w[q,:] + Wc_b[q] + w[q]*t[b]
// fp32 SIMT GEMM, 64x64 tile, 256 threads, 4x4 register tile, TK=32
// ---------------------------------------------------------------------------
__global__ __launch_bounds__(256) void angle_kernel(
    const float* __restrict__ X0, const float* __restrict__ W,
    const float* __restrict__ bias, const float* __restrict__ wvec,
    const float* __restrict__ tvec)
{
    __shared__ float Xs[32][64];   // [kk][row]
    __shared__ float Ws[32][64];   // [kk][q]

    int tid = threadIdx.x;
    int r0  = blockIdx.x * 64;
    int q0  = blockIdx.y * 64;
    int lr  = tid >> 2;            // 0..63 : row/q being loaded
    int lc  = (tid & 3) * 8;       // 0,8,16,24 : k-offset being loaded
    int rt  = tid & 15;            // row tile group (rows rt*4..rt*4+3)
    int ct  = tid >> 4;            // q tile group (q ct*4..ct*4+3)

    float acc[4][4] = {};

    for (int kb = 0; kb < DIN; kb += 32) {
        float4 xa = *(const float4*)&X0[(r0 + lr) * DIN + kb + lc];
        float4 xb = *(const float4*)&X0[(r0 + lr) * DIN + kb + lc + 4];
        float4 wa = *(const float4*)&W [(q0 + lr) * DIN + kb + lc];
        float4 wb = *(const float4*)&W [(q0 + lr) * DIN + kb + lc + 4];
        __syncthreads();           // previous iteration's reads complete
        Xs[lc+0][lr]=xa.x; Xs[lc+1][lr]=xa.y; Xs[lc+2][lr]=xa.z; Xs[lc+3][lr]=xa.w;
        Xs[lc+4][lr]=xb.x; Xs[lc+5][lr]=xb.y; Xs[lc+6][lr]=xb.z; Xs[lc+7][lr]=xb.w;
        Ws[lc+0][lr]=wa.x; Ws[lc+1][lr]=wa.y; Ws[lc+2][lr]=wa.z; Ws[lc+3][lr]=wa.w;
        Ws[lc+4][lr]=wb.x; Ws[lc+5][lr]=wb.y; Ws[lc+6][lr]=wb.z; Ws[lc+7][lr]=wb.w;
        __syncthreads();
        #pragma unroll
        for (int kk = 0; kk < 32; kk++) {
            float4 a4 = *(float4*)&Xs[kk][rt * 4];
            float4 b4 = *(float4*)&Ws[kk][ct * 4];
            acc[0][0] = fmaf(a4.x, b4.x, acc[0][0]);
            acc[0][1] = fmaf(a4.x, b4.y, acc[0][1]);
            acc[0][2] = fmaf(a4.x, b4.z, acc[0][2]);
            acc[0][3] = fmaf(a4.x, b4.w, acc[0][3]);
            acc[1][0] = fmaf(a4.y, b4.x, acc[1][0]);
            acc[1][1] = fmaf(a4.y, b4.y, acc[1][1]);
            acc[1][2] = fmaf(a4.y, b4.z, acc[1][2]);
            acc[1][3] = fmaf(a4.y, b4.w, acc[1][3]);
            acc[2][0] = fmaf(a4.z, b4.x, acc[2][0]);
            acc[2][1] = fmaf(a4.z, b4.y, acc[2][1]);
            acc[2][2] = fmaf(a4.z, b4.z, acc[2][2]);
            acc[2][3] = fmaf(a4.z, b4.w, acc[2][3]);
            acc[3][0] = fmaf(a4.w, b4.x, acc[3][0]);
            acc[3][1] = fmaf(a4.w, b4.y, acc[3][1]);
            acc[3][2] = fmaf(a4.w, b4.z, acc[3][2]);
            acc[3][3] = fmaf(a4.w, b4.w, acc[3][3]);
        }
    }

    #pragma unroll
    for (int i = 0; i < 4; i++) {
        int rg = r0 + rt * 4 + i;
        float tb = tvec[rg >> 10];          // t[b], b = row/1024
        #pragma unroll
        for (int j = 0; j < 4; j++) {
            int qg = q0 + ct * 4 + j;
            g_angle[rg * Q_ + qg] = acc[i][j] + bias[qg] + wvec[qg] * tb;
        }
    }
}

// ---------------------------------------------------------------------------
// Kernel 3: fused feature-gen + GEMM2.
// Each block: 32 rows. Loop over 16 q-chunks of 8 q's (96 features each):
//   - copy Afold chunk [96][64] to smem
//   - 256 threads each do one (row,q): Cody-Waite reduce, __sincosf,
//     angle-addition recurrence -> 12 features into featT[96][32]
//   - rank-96 update of the V[32][64] accumulator tile (2x4 per thread)
// ---------------------------------------------------------------------------
__global__ __launch_bounds__(256) void fuse_kernel(float* __restrict__ out)
{
    __shared__ float featT[96][32];   // [f][row]  12 KB
    __shared__ float afs[96][64];     // [f][d]    24 KB

    int tid = threadIdx.x;
    int r0  = blockIdx.x * 32;
    int row = tid & 31;               // feature-gen row
    int ql  = tid >> 5;               // feature-gen local q (0..7)
    int rt  = tid & 15;               // GEMM rows rt*2, rt*2+1
    int ct  = tid >> 4;               // GEMM d group ct*4..ct*4+3

    float acc[2][4] = {};

    for (int qc = 0; qc < 16; qc++) {
        // --- copy Afold chunk (96*64 floats) ---
        const float4* src = (const float4*)(g_afold + qc * 96 * 64);
        float4* dst = (float4*)&afs[0][0];
        #pragma unroll
        for (int i = 0; i < 6; i++) dst[tid + 256 * i] = src[tid + 256 * i];

        // --- features for q = qc*8 + ql ---
        int q = qc * 8 + ql;
        float a = g_angle[(r0 + row) * Q_ + q];
        // 2-term Cody-Waite reduction mod 2*pi (C1 = 6.28125 has 9 mantissa
        // bits -> n*C1 exact for |n| < 2^15; a - n*C1 exact by cancellation)
        float n = rintf(a * 0.15915494309189535f);
        float r = fmaf(n, -6.28125f, a);
        r = fmaf(n, -1.9353071795864769e-3f, r);
        float s1, c1;
        __sincosf(r, &s1, &c1);       // |r| <= pi: full fast-path accuracy
        float sk = s1, ck = c1;
        int base = ql * 12;
        featT[base + 0][row] = sk;
        featT[base + 1][row] = ck;
        #pragma unroll
        for (int k = 1; k < KF; k++) {
            float sn = fmaf(sk, c1, ck * s1);   // sin((k+1)a)
            float cn = fmaf(ck, c1, -sk * s1);  // cos((k+1)a)
            featT[base + 2 * k][row]     = sn;
            featT[base + 2 * k + 1][row] = cn;
            sk = sn; ck = cn;
        }
        __syncthreads();

        // --- rank-96 update ---
        #pragma unroll 8
        for (int f = 0; f < 96; f++) {
            float2 a2 = *(float2*)&featT[f][rt * 2];
            float4 b4 = *(float4*)&afs[f][ct * 4];
            acc[0][0] = fmaf(a2.x, b4.x, acc[0][0]);
            acc[0][1] = fmaf(a2.x, b4.y, acc[0][1]);
            acc[0][2] = fmaf(a2.x, b4.z, acc[0][2]);
            acc[0][3] = fmaf(a2.x, b4.w, acc[0][3]);
            acc[1][0] = fmaf(a2.y, b4.x, acc[1][0]);
            acc[1][1] = fmaf(a2.y, b4.y, acc[1][1]);
            acc[1][2] = fmaf(a2.y, b4.z, acc[1][2]);
            acc[1][3] = fmaf(a2.y, b4.w, acc[1][3]);
        }
        __syncthreads();   // guard next iteration's smem overwrite
    }

    #pragma unroll
    for (int i = 0; i < 2; i++) {
        int rg = r0 + rt * 2 + i;
        float4 v = make_float4(acc[i][0], acc[i][1], acc[i][2], acc[i][3]);
        *(float4*)&out[rg * DOUT + ct * 4] = v;
    }
}

// ---------------------------------------------------------------------------
extern "C" void kernel_launch(void* const* d_in, const int* in_sizes, int n_in,
                              void* d_out, int out_size) {
    const float* X0   = (const float*)d_in[0];
    const float* tvec = (const float*)d_in[1];
    const float* Wc_w = (const float*)d_in[2];
    const float* Wc_b = (const float*)d_in[3];
    const float* wvec = (const float*)d_in[4];
    const float* A    = (const float*)d_in[5];
    const float* Bp   = (const float*)d_in[6];
    float* out = (float*)d_out;

    fold_kernel<<<(DOUT * Q_ * KF + 255) / 256, 256>>>(A, Bp);
    angle_kernel<<<dim3(ROWS / 64, Q_ / 64), 256>>>(X0, Wc_w, Wc_b, wvec, tvec);
    fuse_kernel<<<ROWS / 32, 256>>>(out);
}